// round 5
// baseline (speedup 1.0000x reference)
#include <cuda_runtime.h>
#include <cuda_bf16.h>
#include <math.h>
#include <stdint.h>

#define Nn 64
#define T  512
#define Dd 512
#define Hh 512
#define G4 2048   // 4*H
#define NB 128    // persistent blocks (<=148 SMs, co-resident)

// ---------------- scratch (static device arrays) ----------------
__device__ __align__(128) float g_xW[(size_t)Nn * T * G4];          // [t][n][4H]
__device__ __align__(128) __nv_bfloat16 g_hh[2][Nn * Hh];           // h hi plane, [n][hid]
__device__ __align__(128) __nv_bfloat16 g_hl[2][Nn * Hh];           // h lo plane, [n][hid]
__device__ int g_cnt;
__device__ int g_epoch;

// ---------------- helpers ----------------
static __device__ __forceinline__ uint32_t s2u(const void* p) {
    return (uint32_t)__cvta_generic_to_shared(p);
}
static __device__ __forceinline__ void ldsm4(uint32_t* r, uint32_t addr) {
    asm volatile("ldmatrix.sync.aligned.m8n8.x4.shared.b16 {%0,%1,%2,%3}, [%4];"
                 : "=r"(r[0]), "=r"(r[1]), "=r"(r[2]), "=r"(r[3]) : "r"(addr));
}
static __device__ __forceinline__ void mma16816(float* d, const uint32_t* a,
                                                uint32_t b0, uint32_t b1) {
    asm volatile("mma.sync.aligned.m16n8k16.row.col.f32.bf16.bf16.f32 "
                 "{%0,%1,%2,%3},{%4,%5,%6,%7},{%8,%9},{%0,%1,%2,%3};"
                 : "+f"(d[0]), "+f"(d[1]), "+f"(d[2]), "+f"(d[3])
                 : "r"(a[0]), "r"(a[1]), "r"(a[2]), "r"(a[3]), "r"(b0), "r"(b1));
}
static __device__ __forceinline__ void cpasync16(uint32_t dst, const void* src) {
    asm volatile("cp.async.cg.shared.global [%0], [%1], 16;" :: "r"(dst), "l"(src));
}
static __device__ __forceinline__ void cpasync_wait_all() {
    asm volatile("cp.async.commit_group;");
    asm volatile("cp.async.wait_group 0;");
}

// smem layout (bytes)
#define W_HI_OFF   0
#define W_LO_OFF   16640                 // 16 rows * 520 halves * 2B
#define H_HI_OFF   33280
#define H_LO_OFF   (33280 + 66560)       // 64 rows * 520 halves * 2B
#define SACC_OFF   (33280 + 2 * 66560)   // 166400
#define HSTG_OFF   (SACC_OFF + 2 * 16 * 68 * 4)  // 175104
#define SMEM_BYTES (HSTG_OFF + 64 * 4 * 4)       // 176128

// ---------------------------------------------------------------------------
// GEMM 1 (round-3 version): xW = x @ Wx + b, relaid as [t][n][4H].
// 128x128 tile, BK=8, 256 threads, 8x8 FFMA microtile, double-buffered.
// ---------------------------------------------------------------------------
__global__ __launch_bounds__(256) void gemm_xw(const float* __restrict__ x,
                                               const float* __restrict__ Wx,
                                               const float* __restrict__ b) {
    __shared__ float As[2][8][128];
    __shared__ float Bs[2][8][128];

    const int tid = threadIdx.x;
    const int tx = tid & 15;
    const int ty = tid >> 4;
    const int m0 = blockIdx.y * 128;
    const int n0 = blockIdx.x * 128;

    const int a_m = tid >> 1;
    const int a_k = (tid & 1) * 4;
    const int b_c = (tid & 31) * 4;
    const int b_k = tid >> 5;

    float acc[8][8];
#pragma unroll
    for (int i = 0; i < 8; i++)
#pragma unroll
        for (int j = 0; j < 8; j++) acc[i][j] = 0.f;

    float4 pa = *(const float4*)&x[(size_t)(m0 + a_m) * Dd + a_k];
    float4 pb = *(const float4*)&Wx[(size_t)b_k * G4 + n0 + b_c];
    As[0][a_k + 0][a_m] = pa.x;
    As[0][a_k + 1][a_m] = pa.y;
    As[0][a_k + 2][a_m] = pa.z;
    As[0][a_k + 3][a_m] = pa.w;
    *(float4*)&Bs[0][b_k][b_c] = pb;
    __syncthreads();

    const int NSTAGE = Dd / 8;
    for (int s = 0; s < NSTAGE; s++) {
        const int cur = s & 1;
        if (s + 1 < NSTAGE) {
            const int k0 = (s + 1) * 8;
            pa = *(const float4*)&x[(size_t)(m0 + a_m) * Dd + k0 + a_k];
            pb = *(const float4*)&Wx[(size_t)(k0 + b_k) * G4 + n0 + b_c];
        }
#pragma unroll
        for (int k = 0; k < 8; k++) {
            float4 a0 = *(float4*)&As[cur][k][ty * 8];
            float4 a1 = *(float4*)&As[cur][k][ty * 8 + 4];
            float4 b0 = *(float4*)&Bs[cur][k][tx * 8];
            float4 b1 = *(float4*)&Bs[cur][k][tx * 8 + 4];
            float av[8] = {a0.x, a0.y, a0.z, a0.w, a1.x, a1.y, a1.z, a1.w};
            float bv[8] = {b0.x, b0.y, b0.z, b0.w, b1.x, b1.y, b1.z, b1.w};
#pragma unroll
            for (int i = 0; i < 8; i++)
#pragma unroll
                for (int j = 0; j < 8; j++) acc[i][j] += av[i] * bv[j];
        }
        if (s + 1 < NSTAGE) {
            const int nxt = cur ^ 1;
            As[nxt][a_k + 0][a_m] = pa.x;
            As[nxt][a_k + 1][a_m] = pa.y;
            As[nxt][a_k + 2][a_m] = pa.z;
            As[nxt][a_k + 3][a_m] = pa.w;
            *(float4*)&Bs[nxt][b_k][b_c] = pb;
            __syncthreads();
        }
    }

    float4 bb0 = *(const float4*)&b[n0 + tx * 8];
    float4 bb1 = *(const float4*)&b[n0 + tx * 8 + 4];
#pragma unroll
    for (int i = 0; i < 8; i++) {
        int m = m0 + ty * 8 + i;
        int tt = m & (T - 1);
        int nn = m >> 9;
        size_t row = ((size_t)tt * Nn + nn) * G4 + n0 + tx * 8;
        *(float4*)&g_xW[row]     = make_float4(acc[i][0] + bb0.x, acc[i][1] + bb0.y,
                                               acc[i][2] + bb0.z, acc[i][3] + bb0.w);
        *(float4*)&g_xW[row + 4] = make_float4(acc[i][4] + bb1.x, acc[i][5] + bb1.y,
                                               acc[i][6] + bb1.z, acc[i][7] + bb1.w);
    }
}

// ---------------------------------------------------------------------------
// Init: h0 -> bf16 hi/lo planes [n][hid]; reset barrier state.
// ---------------------------------------------------------------------------
__global__ void lstm_init(const float* __restrict__ h0) {
    int i = blockIdx.x * blockDim.x + threadIdx.x;
    if (i < Nn * Hh) {
        float v = h0[i];                      // h0 is [n][hid], same layout
        __nv_bfloat16 hi = __float2bfloat16(v);
        __nv_bfloat16 lo = __float2bfloat16(v - __bfloat162float(hi));
        g_hh[0][i] = hi;
        g_hl[0][i] = lo;
    }
    if (i == 0) { g_cnt = 0; g_epoch = 0; }
}

// ---------------------------------------------------------------------------
// Persistent tensor-core scan. grid=128, block=256 (8 warps).
// Block hb owns 16 cols: c(g,u) = g*512 + hb*4 + u.
// Warp wi: mw = wi&3 (16-batch chunk), ks = wi>>2 (k half).
// D[64n][16c] = h[64][512] @ W[512][16] via bf16 m16n8k16, 3-term hi/lo split.
// ---------------------------------------------------------------------------
__global__ __launch_bounds__(256) void lstm_scan(const float* __restrict__ Wh,
                                                 float* __restrict__ out) {
    extern __shared__ char smem[];
    __nv_bfloat16* w_hi = (__nv_bfloat16*)(smem + W_HI_OFF);   // [16][520]
    __nv_bfloat16* w_lo = (__nv_bfloat16*)(smem + W_LO_OFF);
    __nv_bfloat16* h_hi = (__nv_bfloat16*)(smem + H_HI_OFF);   // [64][520]
    __nv_bfloat16* h_lo = (__nv_bfloat16*)(smem + H_LO_OFF);
    float* sacc   = (float*)(smem + SACC_OFF);                 // [2][16][68]
    float* hstage = (float*)(smem + HSTG_OFF);                 // [64][4]

    const int tid  = threadIdx.x;
    const int hb   = blockIdx.x;
    const int wi   = tid >> 5;
    const int lane = tid & 31;
    const int mw   = wi & 3;        // batch chunk
    const int ks   = wi >> 2;       // k half (0: k<256, 1: k>=256)
    const int u_e  = tid >> 6;      // epilogue: local hidden unit 0..3
    const int n_e  = tid & 63;      // epilogue: batch

    // --- one-time: resident W slice as bf16 hi/lo planes, [c][k], pitch 520 ---
    for (int idx = tid; idx < 16 * 512; idx += 256) {
        int k = idx >> 4;
        int c = idx & 15;
        int g = c >> 2;
        int u = c & 3;
        float w = Wh[(size_t)k * G4 + g * Hh + hb * 4 + u];
        __nv_bfloat16 hi = __float2bfloat16(w);
        __nv_bfloat16 lo = __float2bfloat16(w - __bfloat162float(hi));
        w_hi[c * 520 + k] = hi;
        w_lo[c * 520 + k] = lo;
    }

    // ldmatrix fragment addresses (byte offsets advance 32B per k-chunk)
    const int tile = lane >> 3;
    const int tr   = lane & 7;
    const uint32_t a_row = mw * 16 + (tile & 1) * 8 + tr;
    const uint32_t a_koff = ((tile >> 1) * 8) * 2;              // bytes
    const uint32_t b_c   = (tile >> 1) * 8 + tr;
    const uint32_t b_koff = ((tile & 1) * 8) * 2;
    uint32_t ahi_base = s2u(h_hi) + a_row * 1040 + a_koff;
    uint32_t alo_base = s2u(h_lo) + a_row * 1040 + a_koff;
    uint32_t bhi_base = s2u(w_hi) + b_c * 1040 + b_koff;
    uint32_t blo_base = s2u(w_lo) + b_c * 1040 + b_koff;
    const uint32_t kc0 = ks * 16;   // first k-chunk for this warp

    // staging assignments (16 chunks of 16B per plane per thread)
    // chunk id = tid + p*256 ; row = id>>6 ; k16 = id&63
    float c_reg = 0.f;
    volatile int* vep = &g_epoch;

    __syncthreads();   // W planes ready (first use is after the staging sync anyway)

    for (int t = 0; t < T; t++) {
        const int cur = t & 1;
        const __nv_bfloat16* ghh = g_hh[cur];
        const __nv_bfloat16* ghl = g_hl[cur];

        // prefetch this step's xW gate slice (fp32)
        const float* xwp = g_xW + ((size_t)t * Nn + n_e) * G4 + hb * 4 + u_e;
        float xw0 = xwp[0 * Hh];
        float xw1 = xwp[1 * Hh];
        float xw2 = xwp[2 * Hh];
        float xw3 = xwp[3 * Hh];

        // --- stage h planes into smem (cp.async, 128KB total) ---
#pragma unroll
        for (int p = 0; p < 16; p++) {
            int id  = tid + p * 256;
            int row = id >> 6;
            int k16 = id & 63;
            uint32_t d = row * 1040 + k16 * 16;
            const char* s = (const char*)ghh + row * 1024 + k16 * 16;
            cpasync16(s2u(h_hi) + d, s);
        }
#pragma unroll
        for (int p = 0; p < 16; p++) {
            int id  = tid + p * 256;
            int row = id >> 6;
            int k16 = id & 63;
            uint32_t d = row * 1040 + k16 * 16;
            const char* s = (const char*)ghl + row * 1024 + k16 * 16;
            cpasync16(s2u(h_lo) + d, s);
        }
        cpasync_wait_all();
        __syncthreads();

        // --- tensor-core GEMM: 16 k-chunks per warp, 3-term split ---
        float dm0[4] = {0, 0, 0, 0}, dm1[4] = {0, 0, 0, 0};
        float dc0[4] = {0, 0, 0, 0}, dc1[4] = {0, 0, 0, 0};
#pragma unroll 4
        for (int kc = 0; kc < 16; kc++) {
            const uint32_t off = (kc0 + kc) * 32;
            uint32_t ah[4], al[4], bh[4], bl[4];
            ldsm4(ah, ahi_base + off);
            ldsm4(bh, bhi_base + off);
            ldsm4(al, alo_base + off);
            ldsm4(bl, blo_base + off);
            mma16816(dm0, ah, bh[0], bh[1]);
            mma16816(dm1, ah, bh[2], bh[3]);
            mma16816(dc0, ah, bl[0], bl[1]);
            mma16816(dc1, ah, bl[2], bl[3]);
            mma16816(dc0, al, bh[0], bh[1]);
            mma16816(dc1, al, bh[2], bh[3]);
        }

        // --- D frags -> sacc[ks][c][n], conflict-free pattern ---
        {
            float* sa = sacc + ks * 16 * 68;
            const int m0 = mw * 16 + (lane >> 2);
            const int cA = (lane & 3) * 2;           // ntile 0 cols
#pragma unroll
            for (int nt = 0; nt < 2; nt++) {
                const float* d = nt ? dm1 : dm0;
                const float* e = nt ? dc1 : dc0;
                const int c0 = nt * 8 + cA;
                sa[(c0)     * 68 + m0]     = d[0] + e[0];
                sa[(c0 + 1) * 68 + m0]     = d[1] + e[1];
                sa[(c0)     * 68 + m0 + 8] = d[2] + e[2];
                sa[(c0 + 1) * 68 + m0 + 8] = d[3] + e[3];
            }
        }
        __syncthreads();

        // --- epilogue: thread handles (u_e, n_e) ---
        {
            float ag[4];
#pragma unroll
            for (int g = 0; g < 4; g++) {
                int c = g * 4 + u_e;
                ag[g] = sacc[c * 68 + n_e] + sacc[(16 + c) * 68 + n_e];
            }
            ag[0] += xw0; ag[1] += xw1; ag[2] += xw2; ag[3] += xw3;

            float iv = 1.f / (1.f + expf(-ag[0]));
            float fv = 1.f / (1.f + expf(-ag[1]));
            float ov = 1.f / (1.f + expf(-ag[2]));
            float gv = tanhf(ag[3]);

            c_reg = fv * c_reg + iv * gv;
            float hn = ov * tanhf(c_reg);

            __nv_bfloat16 hi = __float2bfloat16(hn);
            __nv_bfloat16 lo = __float2bfloat16(hn - __bfloat162float(hi));
            const int nxt = cur ^ 1;
            g_hh[nxt][n_e * Hh + hb * 4 + u_e] = hi;
            g_hl[nxt][n_e * Hh + hb * 4 + u_e] = lo;
            hstage[n_e * 4 + u_e] = hn;
        }
        __syncthreads();

        // coalesced out write: out[n][t][hb*4..hb*4+3]
        if (tid < 64)
            *(float4*)&out[((size_t)tid * T + t) * Hh + hb * 4] =
                *(float4*)&hstage[tid * 4];

        // --- grid barrier (epoch t+1) ---
        if (tid == 0) {
            __threadfence();
            int v = atomicAdd(&g_cnt, 1);
            if (v == NB - 1) {
                g_cnt = 0;
                __threadfence();
                *vep = t + 1;
            } else {
                while (*vep < t + 1) { }
            }
            __threadfence();
        }
        __syncthreads();
    }
}

// ---------------------------------------------------------------------------
// Launch
// ---------------------------------------------------------------------------
extern "C" void kernel_launch(void* const* d_in, const int* in_sizes, int n_in,
                              void* d_out, int out_size) {
    const float* x  = (const float*)d_in[0];
    const float* h0 = (const float*)d_in[1];
    const float* Wx = (const float*)d_in[2];
    const float* Wh = (const float*)d_in[3];
    const float* b  = (const float*)d_in[4];
    float* out = (float*)d_out;

    cudaFuncSetAttribute(lstm_scan, cudaFuncAttributeMaxDynamicSharedMemorySize,
                         SMEM_BYTES);

    dim3 g1(G4 / 128, (Nn * T) / 128);
    gemm_xw<<<g1, 256>>>(x, Wx, b);
    lstm_init<<<(Nn * Hh + 255) / 256, 256>>>(h0);
    lstm_scan<<<NB, 256, SMEM_BYTES>>>(Wh, out);
}

// round 6
// speedup vs baseline: 1.2730x; 1.2730x over previous
#include <cuda_runtime.h>
#include <math.h>
#include <stdint.h>

#define Nn 64
#define T  512
#define Dd 512
#define Hh 512
#define G4 2048   // 4*H
#define NB 128    // persistent blocks (<=148 SMs, co-resident)

// ---------------- scratch (static device arrays) ----------------
__device__ __align__(128) float g_xW[(size_t)Nn * T * G4];   // [t][n][4H]
__device__ __align__(128) float g_h[2][Hh * Nn];             // ping-pong hidden, [hidx][n]
__device__ int g_cnt;
__device__ int g_epoch;

// Packed dual-lane fp32 FMA (Blackwell FFMA2; only reachable via PTX f32x2)
__device__ __forceinline__ void fma2(unsigned long long& d,
                                     unsigned long long a,
                                     unsigned long long b) {
    asm("fma.rn.f32x2 %0, %1, %2, %0;" : "+l"(d) : "l"(a), "l"(b));
}
static __device__ __forceinline__ uint32_t s2u(const void* p) {
    return (uint32_t)__cvta_generic_to_shared(p);
}
static __device__ __forceinline__ void cpasync16(uint32_t dst, const void* src) {
    asm volatile("cp.async.cg.shared.global [%0], [%1], 16;" :: "r"(dst), "l"(src));
}

// ---------------------------------------------------------------------------
// GEMM 1 (round-3 version, best measured): xW = x @ Wx + b, relaid [t][n][4H].
// 128x128 tile, BK=8, 256 threads, 8x8 FFMA microtile, double-buffered.
// ---------------------------------------------------------------------------
__global__ __launch_bounds__(256) void gemm_xw(const float* __restrict__ x,
                                               const float* __restrict__ Wx,
                                               const float* __restrict__ b) {
    __shared__ float As[2][8][128];
    __shared__ float Bs[2][8][128];

    const int tid = threadIdx.x;
    const int tx = tid & 15;
    const int ty = tid >> 4;
    const int m0 = blockIdx.y * 128;
    const int n0 = blockIdx.x * 128;

    const int a_m = tid >> 1;
    const int a_k = (tid & 1) * 4;
    const int b_c = (tid & 31) * 4;
    const int b_k = tid >> 5;

    float acc[8][8];
#pragma unroll
    for (int i = 0; i < 8; i++)
#pragma unroll
        for (int j = 0; j < 8; j++) acc[i][j] = 0.f;

    float4 pa = *(const float4*)&x[(size_t)(m0 + a_m) * Dd + a_k];
    float4 pb = *(const float4*)&Wx[(size_t)b_k * G4 + n0 + b_c];
    As[0][a_k + 0][a_m] = pa.x;
    As[0][a_k + 1][a_m] = pa.y;
    As[0][a_k + 2][a_m] = pa.z;
    As[0][a_k + 3][a_m] = pa.w;
    *(float4*)&Bs[0][b_k][b_c] = pb;
    __syncthreads();

    const int NSTAGE = Dd / 8;
    for (int s = 0; s < NSTAGE; s++) {
        const int cur = s & 1;
        if (s + 1 < NSTAGE) {
            const int k0 = (s + 1) * 8;
            pa = *(const float4*)&x[(size_t)(m0 + a_m) * Dd + k0 + a_k];
            pb = *(const float4*)&Wx[(size_t)(k0 + b_k) * G4 + n0 + b_c];
        }
#pragma unroll
        for (int k = 0; k < 8; k++) {
            float4 a0 = *(float4*)&As[cur][k][ty * 8];
            float4 a1 = *(float4*)&As[cur][k][ty * 8 + 4];
            float4 b0 = *(float4*)&Bs[cur][k][tx * 8];
            float4 b1 = *(float4*)&Bs[cur][k][tx * 8 + 4];
            float av[8] = {a0.x, a0.y, a0.z, a0.w, a1.x, a1.y, a1.z, a1.w};
            float bv[8] = {b0.x, b0.y, b0.z, b0.w, b1.x, b1.y, b1.z, b1.w};
#pragma unroll
            for (int i = 0; i < 8; i++)
#pragma unroll
                for (int j = 0; j < 8; j++) acc[i][j] += av[i] * bv[j];
        }
        if (s + 1 < NSTAGE) {
            const int nxt = cur ^ 1;
            As[nxt][a_k + 0][a_m] = pa.x;
            As[nxt][a_k + 1][a_m] = pa.y;
            As[nxt][a_k + 2][a_m] = pa.z;
            As[nxt][a_k + 3][a_m] = pa.w;
            *(float4*)&Bs[nxt][b_k][b_c] = pb;
            __syncthreads();
        }
    }

    float4 bb0 = *(const float4*)&b[n0 + tx * 8];
    float4 bb1 = *(const float4*)&b[n0 + tx * 8 + 4];
#pragma unroll
    for (int i = 0; i < 8; i++) {
        int m = m0 + ty * 8 + i;
        int tt = m & (T - 1);
        int nn = m >> 9;
        size_t row = ((size_t)tt * Nn + nn) * G4 + n0 + tx * 8;
        *(float4*)&g_xW[row]     = make_float4(acc[i][0] + bb0.x, acc[i][1] + bb0.y,
                                               acc[i][2] + bb0.z, acc[i][3] + bb0.w);
        *(float4*)&g_xW[row + 4] = make_float4(acc[i][4] + bb1.x, acc[i][5] + bb1.y,
                                               acc[i][6] + bb1.z, acc[i][7] + bb1.w);
    }
}

// ---------------------------------------------------------------------------
// Init: g_h[0][h][n] = h0[n][h]; reset barrier state.
// ---------------------------------------------------------------------------
__global__ void lstm_init(const float* __restrict__ h0) {
    int i = blockIdx.x * blockDim.x + threadIdx.x;
    if (i < Nn * Hh) {
        int n = i & 63;
        int h = i >> 6;
        g_h[0][h * Nn + n] = h0[n * Hh + h];
    }
    if (i == 0) { g_cnt = 0; g_epoch = 0; }
}

// ---------------------------------------------------------------------------
// Persistent scan (r4 structure + overlapped chunked staging).
// grid=128, block=256. Block hb owns 16 cols (4 hidden x 4 gates).
// Warp-group ks (tid>>6) owns 128 k, remapped as 32 k per 128-k chunk so each
// staging chunk unblocks ALL warps: phase c computes k in
// [c*128 + ks*32, +32) while chunks c+1.. are still in flight (cp.async.cg).
// ---------------------------------------------------------------------------
__global__ __launch_bounds__(256) void lstm_scan(const float* __restrict__ Wh,
                                                 float* __restrict__ out) {
    extern __shared__ float sm[];
    unsigned long long* wsd = (unsigned long long*)sm;   // [512][16] dup pairs (64KB)
    float* hfull  = sm + 512 * 16 * 2;                   // [512][64] (128KB)
    float* sacc   = hfull + 512 * 64;                    // [4][16][66]
    float* hstage = sacc + 4 * 16 * 66;                  // [64][4]

    const int tid = threadIdx.x;
    const int hb  = blockIdx.x;
    const int ks  = tid >> 6;          // k group 0..3
    const int r   = tid & 63;
    const int mq  = r & 15;            // batch group of 4
    const int cq  = r >> 4;            // col group of 4
    const int u_e = tid >> 6;          // epilogue: local hidden unit
    const int n_e = tid & 63;          // epilogue: batch

    // resident Wh slice, duplicated pairs {w,w}
    for (int idx = tid; idx < 512 * 16; idx += 256) {
        int k = idx >> 4;
        int c = idx & 15;
        int g = c >> 2;
        int u = c & 3;
        float w = Wh[(size_t)k * G4 + g * Hh + hb * 4 + u];
        ((float2*)wsd)[idx] = make_float2(w, w);
    }

    const uint32_t h_smem = s2u(hfull);
    float c_reg = 0.f;
    volatile int* vep = &g_epoch;

    for (int t = 0; t < T; t++) {
        const float* hcur = g_h[t & 1];
        float*       hnxt = g_h[(t & 1) ^ 1];

        // prefetch this step's xW gate slice
        const float* xwp = g_xW + ((size_t)t * Nn + n_e) * G4 + hb * 4 + u_e;
        float xw0 = xwp[0 * Hh];
        float xw1 = xwp[1 * Hh];
        float xw2 = xwp[2 * Hh];
        float xw3 = xwp[3 * Hh];

        // --- issue h staging: 4 chunks of 32KB, one commit group each ---
#pragma unroll
        for (int c = 0; c < 4; c++) {
#pragma unroll
            for (int p = 0; p < 8; p++) {
                uint32_t off = (uint32_t)c * 32768u + (uint32_t)(p * 256 + tid) * 16u;
                cpasync16(h_smem + off, (const char*)hcur + off);
            }
            asm volatile("cp.async.commit_group;");
        }

        // --- 4 overlapped GEMM phases ---
        unsigned long long acc00 = 0, acc01 = 0, acc10 = 0, acc11 = 0;
        unsigned long long acc20 = 0, acc21 = 0, acc30 = 0, acc31 = 0;

#define GEMM_PHASE(C, WG)                                                     \
        {                                                                     \
            asm volatile("cp.async.wait_group %0;" :: "n"(WG));               \
            __syncthreads();                                                  \
            const float* hbp = hfull + ((C) * 128 + ks * 32) * 64 + mq * 4;   \
            const unsigned long long* wbp =                                   \
                wsd + ((C) * 128 + ks * 32) * 16 + cq * 4;                    \
            _Pragma("unroll 8")                                               \
            for (int k = 0; k < 32; k++) {                                    \
                ulonglong2 a  = *(const ulonglong2*)(hbp + (size_t)k * 64);   \
                ulonglong2 w0 = *(const ulonglong2*)(wbp + k * 16);           \
                ulonglong2 w1 = *(const ulonglong2*)(wbp + k * 16 + 2);       \
                fma2(acc00, w0.x, a.x); fma2(acc01, w0.x, a.y);               \
                fma2(acc10, w0.y, a.x); fma2(acc11, w0.y, a.y);               \
                fma2(acc20, w1.x, a.x); fma2(acc21, w1.x, a.y);               \
                fma2(acc30, w1.y, a.x); fma2(acc31, w1.y, a.y);               \
            }                                                                 \
        }
        GEMM_PHASE(0, 3)
        GEMM_PHASE(1, 2)
        GEMM_PHASE(2, 1)
        GEMM_PHASE(3, 0)
#undef GEMM_PHASE

        // --- partials -> smem ---
        {
            float* p0 = &sacc[(ks * 16 + cq * 4 + 0) * 66 + mq * 4];
            float* p1 = &sacc[(ks * 16 + cq * 4 + 1) * 66 + mq * 4];
            float* p2 = &sacc[(ks * 16 + cq * 4 + 2) * 66 + mq * 4];
            float* p3 = &sacc[(ks * 16 + cq * 4 + 3) * 66 + mq * 4];
            *(unsigned long long*)(p0)     = acc00;
            *(unsigned long long*)(p0 + 2) = acc01;
            *(unsigned long long*)(p1)     = acc10;
            *(unsigned long long*)(p1 + 2) = acc11;
            *(unsigned long long*)(p2)     = acc20;
            *(unsigned long long*)(p2 + 2) = acc21;
            *(unsigned long long*)(p3)     = acc30;
            *(unsigned long long*)(p3 + 2) = acc31;
        }
        __syncthreads();

        // --- epilogue: thread handles (u_e, n_e) ---
        {
            float ag[4];
#pragma unroll
            for (int g = 0; g < 4; g++) {
                int c = g * 4 + u_e;
                ag[g] = sacc[(0 * 16 + c) * 66 + n_e]
                      + sacc[(1 * 16 + c) * 66 + n_e]
                      + sacc[(2 * 16 + c) * 66 + n_e]
                      + sacc[(3 * 16 + c) * 66 + n_e];
            }
            ag[0] += xw0; ag[1] += xw1; ag[2] += xw2; ag[3] += xw3;

            float iv = 1.f / (1.f + expf(-ag[0]));
            float fv = 1.f / (1.f + expf(-ag[1]));
            float ov = 1.f / (1.f + expf(-ag[2]));
            float gv = tanhf(ag[3]);

            c_reg = fv * c_reg + iv * gv;
            float hn = ov * tanhf(c_reg);

            hnxt[(hb * 4 + u_e) * Nn + n_e] = hn;   // coalesced
            hstage[n_e * 4 + u_e] = hn;
        }
        __syncthreads();

        // coalesced out write: out[n][t][hb*4..hb*4+3]
        if (tid < 64)
            *(float4*)&out[((size_t)tid * T + t) * Hh + hb * 4] =
                *(float4*)&hstage[tid * 4];

        // --- grid barrier (epoch t+1); thread-0 fence flushes L1D (CCTL.IVALL) ---
        if (tid == 0) {
            __threadfence();
            int v = atomicAdd(&g_cnt, 1);
            if (v == NB - 1) {
                g_cnt = 0;
                __threadfence();
                *vep = t + 1;
            } else {
                while (*vep < t + 1) { }
            }
            __threadfence();
        }
        __syncthreads();
    }
}

// ---------------------------------------------------------------------------
// Launch
// ---------------------------------------------------------------------------
extern "C" void kernel_launch(void* const* d_in, const int* in_sizes, int n_in,
                              void* d_out, int out_size) {
    const float* x  = (const float*)d_in[0];
    const float* h0 = (const float*)d_in[1];
    const float* Wx = (const float*)d_in[2];
    const float* Wh = (const float*)d_in[3];
    const float* b  = (const float*)d_in[4];
    float* out = (float*)d_out;

    const int smem = (512 * 16 * 2 + 512 * 64 + 4 * 16 * 66 + 64 * 4) * sizeof(float);
    cudaFuncSetAttribute(lstm_scan, cudaFuncAttributeMaxDynamicSharedMemorySize, smem);

    dim3 g1(G4 / 128, (Nn * T) / 128);
    gemm_xw<<<g1, 256>>>(x, Wx, b);
    lstm_init<<<(Nn * Hh + 255) / 256, 256>>>(h0);
    lstm_scan<<<NB, 256, smem>>>(Wh, out);
}